// round 16
// baseline (speedup 1.0000x reference)
#include <cuda_runtime.h>
#include <cuda_fp16.h>
#include <math.h>

#define TQ    2000
#define KIN   400
#define MAXB  64
#define LOG2E 1.4426950408889634f
#define LN2   0.6931471805599453f
#define ANEG  (-1e7f)
#define PB    0.36787944117144233f  // e^{-1}

// ctc geometry: R=2 super-pairs (4 states)/thread, width-16 shfl groups.
// Group = 16 lanes x 4 states = 64-state renorm window (proven size).
#define KSTEP 8
#define GHALO 4                     // halo lanes per 16-lane group
#define OPG   12                    // owner lanes per group
#define NG    18                    // groups (17 active + 1 inert)
#define NWC   9                     // warps
#define NTC   288
#define UMAX  201                   // super-pairs u = 0..200 (states 4u..4u+3)

#define TTILE 16
#define NTILE 125                   // covers t = 1..1999
#define RS    408

__device__ float g_lse[MAXB * TQ];
// e^{attn} fp16 TRANSPOSED: half index = (b*KIN + col)*TQ + (t-1), t>=1
__device__ uint4 g_ptT[(size_t)MAXB * KIN * TQ / 8];
__device__ float g_losses[MAXB];

__device__ __forceinline__ float ex2(float x) {
    float r; asm("ex2.approx.ftz.f32 %0, %1;" : "=f"(r) : "f"(x)); return r;
}
__device__ __forceinline__ float lg2(float x) {
    float r; asm("lg2.approx.ftz.f32 %0, %1;" : "=f"(r) : "f"(x)); return r;
}
__device__ __forceinline__ float lse2f(float a, float b) {
    return fmaxf(a, b) + lg2(1.f + ex2(-fabsf(a - b)));
}

// ---------------------------------------------------------------------------
// Kernel 1 (unchanged from R15): fused LSE + fp16 e^attn transposed table.
// ---------------------------------------------------------------------------
__global__ void prep_kernel(const float* __restrict__ attn,
                            const int* __restrict__ in_lens,
                            const int* __restrict__ out_lens) {
    __shared__ __half tile[TTILE][RS];
    const int b  = blockIdx.y;
    const int t1 = 1 + TTILE * blockIdx.x;
    const int OL = out_lens[b];
    const int L  = in_lens[b];
    const int w    = threadIdx.x >> 5;
    const int lane = threadIdx.x & 31;

    #pragma unroll
    for (int rr = 0; rr < 2; rr++) {
        const int r = w * 2 + rr;
        const int t = t1 + r;
        if (t <= TQ - 1 && t < OL) {
            const float4* row4 =
                (const float4*)(attn + ((size_t)b * TQ + t) * KIN);
            float s = 0.f;
            for (int k = lane; k < KIN / 4; k += 32) {
                const float4 v = __ldg(row4 + k);
                const float e0 = ex2(v.x * LOG2E);
                const float e1 = ex2(v.y * LOG2E);
                const float e2 = ex2(v.z * LOG2E);
                const float e3 = ex2(v.w * LOG2E);
                const __half2 h01 = __floats2half2_rn(e0, e1);
                const __half2 h23 = __floats2half2_rn(e2, e3);
                uint2 u;
                u.x = *reinterpret_cast<const unsigned*>(&h01);
                u.y = *reinterpret_cast<const unsigned*>(&h23);
                *reinterpret_cast<uint2*>(&tile[r][4 * k]) = u;
                const int base = 4 * k;
                s += (base + 0 < L ? e0 : 0.f) + (base + 1 < L ? e1 : 0.f)
                   + (base + 2 < L ? e2 : 0.f) + (base + 3 < L ? e3 : 0.f);
            }
            #pragma unroll
            for (int o = 16; o; o >>= 1) s += __shfl_xor_sync(0xffffffffu, s, o);
            if (lane == 0) g_lse[b * TQ + t] = lg2(s + PB);
        }
    }
    if (blockIdx.x == 0 && w == 0) {   // t = 0: lse only
        const float4* row4 = (const float4*)(attn + (size_t)b * TQ * KIN);
        float s = 0.f;
        for (int k = lane; k < KIN / 4; k += 32) {
            const float4 v = __ldg(row4 + k);
            const float e0 = ex2(v.x * LOG2E);
            const float e1 = ex2(v.y * LOG2E);
            const float e2 = ex2(v.z * LOG2E);
            const float e3 = ex2(v.w * LOG2E);
            const int base = 4 * k;
            s += (base + 0 < L ? e0 : 0.f) + (base + 1 < L ? e1 : 0.f)
               + (base + 2 < L ? e2 : 0.f) + (base + 3 < L ? e3 : 0.f);
        }
        #pragma unroll
        for (int o = 16; o; o >>= 1) s += __shfl_xor_sync(0xffffffffu, s, o);
        if (lane == 0) g_lse[b * TQ] = lg2(s + PB);
    }
    __syncthreads();

    for (int c = threadIdx.x; c < KIN; c += blockDim.x) {
        unsigned wd[8];
        #pragma unroll
        for (int j = 0; j < 8; j++) {
            const unsigned lo = __half_as_ushort(tile[2 * j][c]);
            const unsigned hi = __half_as_ushort(tile[2 * j + 1][c]);
            wd[j] = lo | (hi << 16);
        }
        const size_t halfbase = ((size_t)b * KIN + c) * TQ + (t1 - 1);
        uint4* dst = g_ptT + (halfbase >> 3);
        dst[0] = make_uint4(wd[0], wd[1], wd[2], wd[3]);
        dst[1] = make_uint4(wd[4], wd[5], wd[6], wd[7]);
    }
}

// ---------------------------------------------------------------------------
// Kernel 2: CTC forward recursion. 288 threads; thread holds super-pair u
// (states E0=4u, O0=4u+1, E1=4u+2, O1=4u+3); u = g*12 + (lane&15) - 4,
// g = 2*warp + (lane>>4); lanes 0-3 of each 16-lane group are halo
// (contamination 1 lane / 2 steps => owners exact after 8 steps). 8 linear
// steps per barrier; ONE width-16 shfl per step serves 4 states. Renorm in
// exponent domain (mantissa + per-group int A), group REDUX max over
// half-warp masks. Emissions: 1 LDG.128 per column per block (transposed
// table). Unnormalized: subtract S = sum lse2 at readout.
// ---------------------------------------------------------------------------
__global__ __launch_bounds__(NTC, 1)
void ctc_kernel(const float* __restrict__ attn,
                const int* __restrict__ in_lens,
                const int* __restrict__ out_lens) {
    __shared__ float4 X[2][UMAX];
    __shared__ int    AsM[2][NG];
    __shared__ float  red[NWC];

    const int b    = blockIdx.x;
    const int tid  = threadIdx.x;
    const int L    = in_lens[b];
    const int OL   = out_lens[b];
    const int lane = tid & 31;
    const int l16  = lane & 15;
    const int g    = (tid >> 4);            // 0..17 (16-lane group id)
    const int u    = g * OPG + l16 - GHALO; // super-pair index [-4, 215]
    const unsigned gmask = (lane < 16) ? 0x0000FFFFu : 0xFFFF0000u;

    const float* lsebase = g_lse + b * TQ;

    // S = sum_{t<OL} lse2[t]
    {
        float s = 0.f;
        for (int t = tid; t < OL; t += NTC) s += lsebase[t];
        #pragma unroll
        for (int o = 16; o; o >>= 1) s += __shfl_xor_sync(0xffffffffu, s, o);
        if (lane == 0) red[tid >> 5] = s;
    }
    __syncthreads();
    float Sval = 0.f;
    if (tid == 0) {
        #pragma unroll
        for (int k = 0; k < NWC; k++) Sval += red[k];
    }

    // token cols for this thread: c0 = 2u (state 4u+1), c1 = 2u+1 (state 4u+3)
    const bool cl0 = (u >= 0) && (2 * u     <= KIN - 1);
    const bool cl1 = (u >= 0) && (2 * u + 1 <= KIN - 1);
    const float mk0 = (cl0 && 2 * u     < L) ? 1.f : 0.f;
    const float mk1 = (cl1 && 2 * u + 1 < L) ? 1.f : 0.f;
    const uint4* pc0 = g_ptT +
        ((((size_t)b * KIN + (cl0 ? 2 * u : 0)) * TQ) >> 3);
    const uint4* pc1 = g_ptT +
        ((((size_t)b * KIN + (cl1 ? 2 * u + 1 : 0)) * TQ) >> 3);

    // init (linear, unnormalized): state0 = e^{-1}, state1 = e^{x00}
    float el0 = 0.f, ol0 = 0.f, el1 = 0.f, ol1 = 0.f;
    int   A   = 0;
    if (u == 0) {
        el0 = PB;
        ol0 = ex2(__ldg(attn + (size_t)b * TQ * KIN) * LOG2E);
    }

    uint4 rv0 = __ldg(pc0);   // col 2u,   t = 1..8
    uint4 rv1 = __ldg(pc1);   // col 2u+1, t = 1..8

    const bool owner = (l16 >= GHALO) && (u <= UMAX - 1);
    const bool inR   = (u >= 0) && (u <= UMAX - 1);
    int gsrc = (u >= 0) ? (u / OPG) : 0;      // group owning super-pair u
    if (gsrc > NG - 1) gsrc = NG - 1;

    const int NB  = (OL - 1) / KSTEP;
    const int rem = (OL - 1) - NB * KSTEP;
    int cb = 0;

    for (int blk = 0; blk < NB; blk++) {
        const uint4 c0 = rv0, c1 = rv1;
        rv0 = __ldg(pc0 + blk + 1);
        rv1 = __ldg(pc1 + blk + 1);

        float pt0[KSTEP], pt1[KSTEP];
        {
            const __half2* h0 = reinterpret_cast<const __half2*>(&c0);
            const __half2* h1 = reinterpret_cast<const __half2*>(&c1);
            #pragma unroll
            for (int j = 0; j < 4; j++) {
                const float2 f0 = __half22float2(h0[j]);
                const float2 f1 = __half22float2(h1[j]);
                pt0[2 * j] = f0.x * mk0;  pt0[2 * j + 1] = f0.y * mk0;
                pt1[2 * j] = f1.x * mk1;  pt1[2 * j + 1] = f1.y * mk1;
            }
        }

        // 8 linear steps; ONE width-16 shfl per step (reads OLD ol1)
        #pragma unroll
        for (int j = 0; j < KSTEP; j++) {
            const float prevO = __shfl_up_sync(0xffffffffu, ol1, 1, 16);
            const float h0 = el0 + prevO;     // ol0 still OLD here
            const float h1 = el1 + ol0;       // uses OLD ol0
            ol0 = (h0 + ol0) * pt0[j];
            ol1 = (h1 + ol1) * pt1[j];
            el0 = h0 * PB;
            el1 = h1 * PB;
        }

        // publish mantissas + group exponent
        if (owner) X[cb][u] = make_float4(el0, ol0, el1, ol1);
        if (l16 == GHALO) AsM[cb][g] = A;
        __syncthreads();
        float4 V = inR ? X[cb][u] : make_float4(0.f, 0.f, 0.f, 0.f);
        el0 = V.x; ol0 = V.y; el1 = V.z; ol1 = V.w;
        const int Al = AsM[cb][gsrc];

        // exponent-domain renorm over the 16-lane group
        const int b0 = (int)((__float_as_uint(el0) >> 23) & 0xFFu);
        const int b1 = (int)((__float_as_uint(ol0) >> 23) & 0xFFu);
        const int b2 = (int)((__float_as_uint(el1) >> 23) & 0xFFu);
        const int b3 = (int)((__float_as_uint(ol1) >> 23) & 0xFFu);
        int be = b0 > b1 ? b0 : b1;
        be = be > b2 ? be : b2;
        be = be > b3 ? be : b3;
        const int key  = Al + be;
        const int kmax = __reduce_max_sync(gmask, key);
        const int An   = kmax - 127;
        const int sft  = Al - An;
        const float factor =
            (sft >= -126) ? __int_as_float((unsigned)(127 + sft) << 23) : 0.f;
        el0 *= factor; ol0 *= factor; el1 *= factor; ol1 *= factor;
        A = An;
        cb ^= 1;
    }

    if (rem > 0) {   // ragged tail: t = 1+NB*KSTEP .. OL-1
        const __half2* h0 = reinterpret_cast<const __half2*>(&rv0);
        const __half2* h1 = reinterpret_cast<const __half2*>(&rv1);
        for (int j = 0; j < rem; j++) {
            const float2 f0 = __half22float2(h0[j >> 1]);
            const float2 f1 = __half22float2(h1[j >> 1]);
            const float p0 = ((j & 1) ? f0.y : f0.x) * mk0;
            const float p1 = ((j & 1) ? f1.y : f1.x) * mk1;
            const float prevO = __shfl_up_sync(0xffffffffu, ol1, 1, 16);
            const float hh0 = el0 + prevO;
            const float hh1 = el1 + ol0;
            ol0 = (hh0 + ol0) * p0;
            ol1 = (hh1 + ol1) * p1;
            el0 = hh0 * PB;
            el1 = hh1 * PB;
        }
    }

    // final publish + readout
    if (owner) X[cb][u] = make_float4(el0, ol0, el1, ol1);
    if (l16 == GHALO) AsM[cb][g] = A;
    __syncthreads();
    if (tid == 0) {
        const int s1 = 2 * L, s2 = 2 * L - 1;
        const float4 Va = X[cb][s1 >> 2];
        const float4 Vb = X[cb][s2 >> 2];
        const float mants1[4] = {Va.x, Va.y, Va.z, Va.w};
        const float mants2[4] = {Vb.x, Vb.y, Vb.z, Vb.w};
        const float m1 = mants1[s1 & 3];
        const float m2 = mants2[s2 & 3];
        const int   A1 = AsM[cb][(s1 >> 2) / OPG];
        const int   A2 = AsM[cb][(s2 >> 2) / OPG];
        const float a1 = fmaxf(lg2(m1) + (float)A1, ANEG);
        const float a2 = fmaxf(lg2(m2) + (float)A2, ANEG);
        const float ll = (lse2f(a1, a2) - Sval) * LN2;
        float loss = -ll / (float)L;
        if (!(ll > -1e6f) || !isfinite(loss)) loss = 0.f;
        g_losses[b] = loss;
    }
}

// ---------------------------------------------------------------------------
// Kernel 3: mean over batch -> scalar
// ---------------------------------------------------------------------------
__global__ void reduce_kernel(float* __restrict__ out, int B) {
    float s = 0.f;
    for (int k = threadIdx.x; k < B; k += 32) s += g_losses[k];
    #pragma unroll
    for (int o = 16; o; o >>= 1) s += __shfl_xor_sync(0xffffffffu, s, o);
    if (threadIdx.x == 0) out[0] = s / (float)B;
}

extern "C" void kernel_launch(void* const* d_in, const int* in_sizes, int n_in,
                              void* d_out, int out_size) {
    const float* attn     = (const float*)d_in[0];
    const int*   in_lens  = (const int*)d_in[1];
    const int*   out_lens = (const int*)d_in[2];
    int B = in_sizes[1];
    if (B > MAXB) B = MAXB;

    dim3 pgrid(NTILE, B);
    prep_kernel<<<pgrid, 256>>>(attn, in_lens, out_lens);
    ctc_kernel<<<B, NTC>>>(attn, in_lens, out_lens);
    reduce_kernel<<<1, 32>>>((float*)d_out, B);
}

// round 17
// speedup vs baseline: 1.0499x; 1.0499x over previous
#include <cuda_runtime.h>
#include <cuda_fp16.h>
#include <math.h>

#define TQ    2000
#define TQP   2048                  // padded per-column t-stride (halfs)
#define KIN   400
#define MAXB  64
#define LOG2E 1.4426950408889634f
#define LN2   0.6931471805599453f
#define ANEG  (-1e7f)
#define PB    0.36787944117144233f  // e^{-1}

// ctc geometry: 4 states/thread, 16-lane groups (64-state window, proven),
// KSTEP=16 steps per barrier (halo 8 lanes: 2 states/step contamination).
#define KSTEP 16
#define GHALO 8
#define OPG   8                     // owner lanes per group
#define NG    26                    // groups
#define NWC   13                    // warps
#define NTC   416
#define UMAX  201                   // super-pairs u = 0..200 (states 4u..4u+3)

#define TTILE 16
#define NTILE 125                   // covers t = 1..1999

__device__ float g_lse[MAXB * TQ];
// e^{attn} fp16 TRANSPOSED: half index = (b*KIN + col)*TQP + (t-1), t>=1
__device__ uint4 g_ptT[(size_t)MAXB * KIN * TQP / 8];
__device__ float g_losses[MAXB];

__device__ __forceinline__ float ex2(float x) {
    float r; asm("ex2.approx.ftz.f32 %0, %1;" : "=f"(r) : "f"(x)); return r;
}
__device__ __forceinline__ float lg2(float x) {
    float r; asm("lg2.approx.ftz.f32 %0, %1;" : "=f"(r) : "f"(x)); return r;
}
__device__ __forceinline__ float lse2f(float a, float b) {
    return fmaxf(a, b) + lg2(1.f + ex2(-fabsf(a - b)));
}

// ---------------------------------------------------------------------------
// Kernel 1: fused LSE + fp16 e^attn transposed table (stride TQP).
// ---------------------------------------------------------------------------
__global__ void prep_kernel(const float* __restrict__ attn,
                            const int* __restrict__ in_lens,
                            const int* __restrict__ out_lens) {
    __shared__ __half tile[TTILE][408];
    const int b  = blockIdx.y;
    const int t1 = 1 + TTILE * blockIdx.x;
    const int OL = out_lens[b];
    const int L  = in_lens[b];
    const int w    = threadIdx.x >> 5;
    const int lane = threadIdx.x & 31;

    #pragma unroll
    for (int rr = 0; rr < 2; rr++) {
        const int r = w * 2 + rr;
        const int t = t1 + r;
        if (t <= TQ - 1 && t < OL) {
            const float4* row4 =
                (const float4*)(attn + ((size_t)b * TQ + t) * KIN);
            float s = 0.f;
            for (int k = lane; k < KIN / 4; k += 32) {
                const float4 v = __ldg(row4 + k);
                const float e0 = ex2(v.x * LOG2E);
                const float e1 = ex2(v.y * LOG2E);
                const float e2 = ex2(v.z * LOG2E);
                const float e3 = ex2(v.w * LOG2E);
                const __half2 h01 = __floats2half2_rn(e0, e1);
                const __half2 h23 = __floats2half2_rn(e2, e3);
                uint2 u;
                u.x = *reinterpret_cast<const unsigned*>(&h01);
                u.y = *reinterpret_cast<const unsigned*>(&h23);
                *reinterpret_cast<uint2*>(&tile[r][4 * k]) = u;
                const int base = 4 * k;
                s += (base + 0 < L ? e0 : 0.f) + (base + 1 < L ? e1 : 0.f)
                   + (base + 2 < L ? e2 : 0.f) + (base + 3 < L ? e3 : 0.f);
            }
            #pragma unroll
            for (int o = 16; o; o >>= 1) s += __shfl_xor_sync(0xffffffffu, s, o);
            if (lane == 0) g_lse[b * TQ + t] = lg2(s + PB);
        }
    }
    if (blockIdx.x == 0 && w == 0) {   // t = 0: lse only
        const float4* row4 = (const float4*)(attn + (size_t)b * TQ * KIN);
        float s = 0.f;
        for (int k = lane; k < KIN / 4; k += 32) {
            const float4 v = __ldg(row4 + k);
            const float e0 = ex2(v.x * LOG2E);
            const float e1 = ex2(v.y * LOG2E);
            const float e2 = ex2(v.z * LOG2E);
            const float e3 = ex2(v.w * LOG2E);
            const int base = 4 * k;
            s += (base + 0 < L ? e0 : 0.f) + (base + 1 < L ? e1 : 0.f)
               + (base + 2 < L ? e2 : 0.f) + (base + 3 < L ? e3 : 0.f);
        }
        #pragma unroll
        for (int o = 16; o; o >>= 1) s += __shfl_xor_sync(0xffffffffu, s, o);
        if (lane == 0) g_lse[b * TQ] = lg2(s + PB);
    }
    __syncthreads();

    for (int c = threadIdx.x; c < KIN; c += blockDim.x) {
        unsigned wd[8];
        #pragma unroll
        for (int j = 0; j < 8; j++) {
            const unsigned lo = __half_as_ushort(tile[2 * j][c]);
            const unsigned hi = __half_as_ushort(tile[2 * j + 1][c]);
            wd[j] = lo | (hi << 16);
        }
        const size_t halfbase = ((size_t)b * KIN + c) * TQP + (t1 - 1);
        uint4* dst = g_ptT + (halfbase >> 3);
        dst[0] = make_uint4(wd[0], wd[1], wd[2], wd[3]);
        dst[1] = make_uint4(wd[4], wd[5], wd[6], wd[7]);
    }
}

// ---------------------------------------------------------------------------
// Kernel 2: CTC forward recursion. 416 threads; thread holds super-pair u
// (states 4u..4u+3); u = g*8 + (lane&15) - 8, g = 2*warp + (lane>>4);
// lanes 0-7 of each 16-lane group are halo (contamination 2 states/step =>
// owners exact after 16 steps). 16 linear steps per barrier (125 barriers
// total). Renorm in exponent domain per 16-lane group (64-state window).
// Emissions: 2x LDG.128 per column per block. Unnormalized: subtract
// S = sum lse2 at readout.
// ---------------------------------------------------------------------------
__global__ __launch_bounds__(NTC, 1)
void ctc_kernel(const float* __restrict__ attn,
                const int* __restrict__ in_lens,
                const int* __restrict__ out_lens) {
    __shared__ float4 X[2][UMAX];
    __shared__ int    AsM[2][NG];
    __shared__ float  red[NWC];

    const int b    = blockIdx.x;
    const int tid  = threadIdx.x;
    const int L    = in_lens[b];
    const int OL   = out_lens[b];
    const int lane = tid & 31;
    const int l16  = lane & 15;
    const int g    = (tid >> 4);            // 0..25
    const int u    = g * OPG + l16 - GHALO; // super-pair index [-8, 207]
    const unsigned gmask = (lane < 16) ? 0x0000FFFFu : 0xFFFF0000u;

    const float* lsebase = g_lse + b * TQ;

    // S = sum_{t<OL} lse2[t]
    {
        float s = 0.f;
        for (int t = tid; t < OL; t += NTC) s += lsebase[t];
        #pragma unroll
        for (int o = 16; o; o >>= 1) s += __shfl_xor_sync(0xffffffffu, s, o);
        if (lane == 0) red[tid >> 5] = s;
    }
    __syncthreads();
    float Sval = 0.f;
    if (tid == 0) {
        #pragma unroll
        for (int k = 0; k < NWC; k++) Sval += red[k];
    }

    // token cols: c0 = 2u (state 4u+1), c1 = 2u+1 (state 4u+3)
    const bool cl0 = (u >= 0) && (2 * u     <= KIN - 1);
    const bool cl1 = (u >= 0) && (2 * u + 1 <= KIN - 1);
    const float mk0 = (cl0 && 2 * u     < L) ? 1.f : 0.f;
    const float mk1 = (cl1 && 2 * u + 1 < L) ? 1.f : 0.f;
    const uint4* pc0 = g_ptT +
        ((((size_t)b * KIN + (cl0 ? 2 * u : 0)) * TQP) >> 3);
    const uint4* pc1 = g_ptT +
        ((((size_t)b * KIN + (cl1 ? 2 * u + 1 : 0)) * TQP) >> 3);

    // init (linear, unnormalized): state0 = e^{-1}, state1 = e^{x00}
    float el0 = 0.f, ol0 = 0.f, el1 = 0.f, ol1 = 0.f;
    int   A   = 0;
    if (u == 0) {
        el0 = PB;
        ol0 = ex2(__ldg(attn + (size_t)b * TQ * KIN) * LOG2E);
    }

    // prefetch t = 1..16 (two uint4 per column)
    uint4 r0a = __ldg(pc0),     r0b = __ldg(pc0 + 1);
    uint4 r1a = __ldg(pc1),     r1b = __ldg(pc1 + 1);

    const bool owner = (l16 >= GHALO) && (u <= UMAX - 1);
    const bool inR   = (u >= 0) && (u <= UMAX - 1);
    int gsrc = (u >= 0) ? (u / OPG) : 0;
    if (gsrc > NG - 1) gsrc = NG - 1;

    const int NB  = (OL - 1) / KSTEP;
    const int rem = (OL - 1) - NB * KSTEP;
    int cb = 0;

    for (int blk = 0; blk < NB; blk++) {
        const uint4 c0a = r0a, c0b = r0b, c1a = r1a, c1b = r1b;
        r0a = __ldg(pc0 + 2 * blk + 2);  r0b = __ldg(pc0 + 2 * blk + 3);
        r1a = __ldg(pc1 + 2 * blk + 2);  r1b = __ldg(pc1 + 2 * blk + 3);

        float pt0[KSTEP], pt1[KSTEP];
        {
            const __half2* h0a = reinterpret_cast<const __half2*>(&c0a);
            const __half2* h0b = reinterpret_cast<const __half2*>(&c0b);
            const __half2* h1a = reinterpret_cast<const __half2*>(&c1a);
            const __half2* h1b = reinterpret_cast<const __half2*>(&c1b);
            #pragma unroll
            for (int j = 0; j < 4; j++) {
                float2 f;
                f = __half22float2(h0a[j]);
                pt0[2*j] = f.x * mk0;      pt0[2*j+1] = f.y * mk0;
                f = __half22float2(h0b[j]);
                pt0[8+2*j] = f.x * mk0;    pt0[8+2*j+1] = f.y * mk0;
                f = __half22float2(h1a[j]);
                pt1[2*j] = f.x * mk1;      pt1[2*j+1] = f.y * mk1;
                f = __half22float2(h1b[j]);
                pt1[8+2*j] = f.x * mk1;    pt1[8+2*j+1] = f.y * mk1;
            }
        }

        // 16 linear steps; one width-16 shfl per step
        #pragma unroll
        for (int j = 0; j < KSTEP; j++) {
            const float prevO = __shfl_up_sync(0xffffffffu, ol1, 1, 16);
            const float h0 = el0 + prevO;
            const float h1 = el1 + ol0;      // uses OLD ol0
            ol0 = (h0 + ol0) * pt0[j];
            ol1 = (h1 + ol1) * pt1[j];
            el0 = h0 * PB;
            el1 = h1 * PB;
        }

        // publish mantissas + group exponent
        if (owner) X[cb][u] = make_float4(el0, ol0, el1, ol1);
        if (l16 == GHALO) AsM[cb][g] = A;
        __syncthreads();
        float4 V = inR ? X[cb][u] : make_float4(0.f, 0.f, 0.f, 0.f);
        el0 = V.x; ol0 = V.y; el1 = V.z; ol1 = V.w;
        const int Al = AsM[cb][gsrc];

        // exponent-domain renorm over the 16-lane group
        const int b0 = (int)((__float_as_uint(el0) >> 23) & 0xFFu);
        const int b1 = (int)((__float_as_uint(ol0) >> 23) & 0xFFu);
        const int b2 = (int)((__float_as_uint(el1) >> 23) & 0xFFu);
        const int b3 = (int)((__float_as_uint(ol1) >> 23) & 0xFFu);
        int be = b0 > b1 ? b0 : b1;
        be = be > b2 ? be : b2;
        be = be > b3 ? be : b3;
        const int key  = Al + be;
        const int kmax = __reduce_max_sync(gmask, key);
        const int An   = kmax - 127;
        const int sft  = Al - An;
        const float factor =
            (sft >= -126) ? __int_as_float((unsigned)(127 + sft) << 23) : 0.f;
        el0 *= factor; ol0 *= factor; el1 *= factor; ol1 *= factor;
        A = An;
        cb ^= 1;
    }

    if (rem > 0) {   // ragged tail: t = 1+NB*KSTEP .. OL-1 (<=15 steps)
        const __half2* h0a = reinterpret_cast<const __half2*>(&r0a);
        const __half2* h0b = reinterpret_cast<const __half2*>(&r0b);
        const __half2* h1a = reinterpret_cast<const __half2*>(&r1a);
        const __half2* h1b = reinterpret_cast<const __half2*>(&r1b);
        for (int j = 0; j < rem; j++) {
            const float2 f0 = __half22float2(j < 8 ? h0a[j >> 1]
                                                   : h0b[(j - 8) >> 1]);
            const float2 f1 = __half22float2(j < 8 ? h1a[j >> 1]
                                                   : h1b[(j - 8) >> 1]);
            const float p0 = ((j & 1) ? f0.y : f0.x) * mk0;
            const float p1 = ((j & 1) ? f1.y : f1.x) * mk1;
            const float prevO = __shfl_up_sync(0xffffffffu, ol1, 1, 16);
            const float hh0 = el0 + prevO;
            const float hh1 = el1 + ol0;
            ol0 = (hh0 + ol0) * p0;
            ol1 = (hh1 + ol1) * p1;
            el0 = hh0 * PB;
            el1 = hh1 * PB;
        }
    }

    // final publish + readout
    if (owner) X[cb][u] = make_float4(el0, ol0, el1, ol1);
    if (l16 == GHALO) AsM[cb][g] = A;
    __syncthreads();
    if (tid == 0) {
        const int s1 = 2 * L, s2 = 2 * L - 1;
        const float4 Va = X[cb][s1 >> 2];
        const float4 Vb = X[cb][s2 >> 2];
        const float mants1[4] = {Va.x, Va.y, Va.z, Va.w};
        const float mants2[4] = {Vb.x, Vb.y, Vb.z, Vb.w};
        const float m1 = mants1[s1 & 3];
        const float m2 = mants2[s2 & 3];
        const int   A1 = AsM[cb][(s1 >> 2) / OPG];
        const int   A2 = AsM[cb][(s2 >> 2) / OPG];
        const float a1 = fmaxf(lg2(m1) + (float)A1, ANEG);
        const float a2 = fmaxf(lg2(m2) + (float)A2, ANEG);
        const float ll = (lse2f(a1, a2) - Sval) * LN2;
        float loss = -ll / (float)L;
        if (!(ll > -1e6f) || !isfinite(loss)) loss = 0.f;
        g_losses[b] = loss;
    }
}

// ---------------------------------------------------------------------------
// Kernel 3: mean over batch -> scalar
// ---------------------------------------------------------------------------
__global__ void reduce_kernel(float* __restrict__ out, int B) {
    float s = 0.f;
    for (int k = threadIdx.x; k < B; k += 32) s += g_losses[k];
    #pragma unroll
    for (int o = 16; o; o >>= 1) s += __shfl_xor_sync(0xffffffffu, s, o);
    if (threadIdx.x == 0) out[0] = s / (float)B;
}

extern "C" void kernel_launch(void* const* d_in, const int* in_sizes, int n_in,
                              void* d_out, int out_size) {
    const float* attn     = (const float*)d_in[0];
    const int*   in_lens  = (const int*)d_in[1];
    const int*   out_lens = (const int*)d_in[2];
    int B = in_sizes[1];
    if (B > MAXB) B = MAXB;

    dim3 pgrid(NTILE, B);
    prep_kernel<<<pgrid, 256>>>(attn, in_lens, out_lens);
    ctc_kernel<<<B, NTC>>>(attn, in_lens, out_lens);
    reduce_kernel<<<1, 32>>>((float*)d_out, B);
}